// round 1
// baseline (speedup 1.0000x reference)
#include <cuda_runtime.h>
#include <cstdint>

// GraphSageLayer: out[b,h] = relu( sum_k concat(self, mean_neigh)[b,k] * W[k,h] )
// B=50000, S=10, D=128, H=128, K=2D=256.
//
// Fused single kernel:
//   phase 1: stage W[256][128] (128KB) into smem (all-L2 hits after wave 1)
//   phase 2: gather tile of 64 rows: self feats + mean of 10 neighbor feats
//            into smem "cm" [64][260] (stride 260 = bank-conflict-free broadcast)
//   phase 3: register-blocked GEMM, 4 rows x 8 cols per thread, packed
//            fma.rn.f32x2 (2 FMAs / instruction — ptxas won't emit from C++)

#define TILE_M    64
#define NTHREADS  256
#define K_DIM     256
#define H_DIM     128
#define CM_STRIDE 260   // 64*260*4 = 66560 B; rows 16B-aligned, odd/32 bank spread

#define SMEM_BYTES ((K_DIM * H_DIM + TILE_M * CM_STRIDE) * 4)

__device__ __forceinline__ unsigned long long fma2(unsigned long long a,
                                                   unsigned long long b,
                                                   unsigned long long c) {
    unsigned long long d;
    asm("fma.rn.f32x2 %0, %1, %2, %3;" : "=l"(d) : "l"(a), "l"(b), "l"(c));
    return d;
}

__device__ __forceinline__ unsigned long long pack2(float a) {
    unsigned long long d;
    asm("mov.b64 %0, {%1, %1};" : "=l"(d) : "f"(a));
    return d;
}

__device__ __forceinline__ void unpack2(unsigned long long v, float& lo, float& hi) {
    asm("mov.b64 {%0, %1}, %2;" : "=f"(lo), "=f"(hi) : "l"(v));
}

__global__ __launch_bounds__(NTHREADS, 1)
void sage_fused_kernel(const int* __restrict__ nodes,
                       const int* __restrict__ neigh,
                       const float* __restrict__ feat,
                       const float* __restrict__ weight,
                       float* __restrict__ out,
                       int Bn)
{
    extern __shared__ float smem[];
    float* sw = smem;                       // [256][128] = 131072 B
    float* cm = smem + K_DIM * H_DIM;       // [64][260]

    const int t = threadIdx.x;
    const int rowBase = blockIdx.x * TILE_M;

    // ---- phase 1: weight -> smem (8192 float4, 32 per thread, coalesced) ----
    {
        const float4* w4 = (const float4*)weight;
        float4* sw4 = (float4*)sw;
        #pragma unroll
        for (int i = 0; i < 32; ++i)
            sw4[t + i * NTHREADS] = w4[t + i * NTHREADS];
    }

    // ---- phase 2: gather. 4 threads per row, each covers 32 dims (8 float4) ----
    {
        const int r = t >> 2;        // 0..63 local row
        const int q = t & 3;         // dim quarter
        const int b = rowBase + r;
        if (b < Bn) {
            const float4* f4 = (const float4*)feat;      // 32 float4 per feature row
            const int node = nodes[b];
            float4* cmSelf = (float4*)&cm[r * CM_STRIDE + q * 32];
            float4* cmMean = (float4*)&cm[r * CM_STRIDE + 128 + q * 32];

            const float4* srow = f4 + (size_t)node * 32 + q * 8;
            #pragma unroll
            for (int j = 0; j < 8; ++j)
                cmSelf[j] = srow[j];

            float4 acc[8];
            #pragma unroll
            for (int j = 0; j < 8; ++j)
                acc[j] = make_float4(0.f, 0.f, 0.f, 0.f);

            #pragma unroll
            for (int s = 0; s < 10; ++s) {
                const int ni = neigh[b * 10 + s];
                const float4* nrow = f4 + (size_t)ni * 32 + q * 8;
                #pragma unroll
                for (int j = 0; j < 8; ++j) {
                    float4 v = nrow[j];
                    acc[j].x += v.x; acc[j].y += v.y;
                    acc[j].z += v.z; acc[j].w += v.w;
                }
            }
            const float inv = 0.1f;
            #pragma unroll
            for (int j = 0; j < 8; ++j) {
                float4 m;
                m.x = acc[j].x * inv; m.y = acc[j].y * inv;
                m.z = acc[j].z * inv; m.w = acc[j].w * inv;
                cmMean[j] = m;
            }
        }
    }
    __syncthreads();

    // ---- phase 3: GEMM. thread (tx,ty): rows ty*4..+3, cols {tx*4..+3, 64+tx*4..+3} ----
    {
        const int tx = t & 15;
        const int ty = t >> 4;

        unsigned long long acc2[4][4];
        #pragma unroll
        for (int i = 0; i < 4; ++i)
            #pragma unroll
            for (int j = 0; j < 4; ++j)
                acc2[i][j] = 0ull;   // packed (0.f, 0.f)

        const float* a0 = &cm[(ty * 4 + 0) * CM_STRIDE];
        const float* a1 = &cm[(ty * 4 + 1) * CM_STRIDE];
        const float* a2p = &cm[(ty * 4 + 2) * CM_STRIDE];
        const float* a3 = &cm[(ty * 4 + 3) * CM_STRIDE];

        #pragma unroll 4
        for (int k = 0; k < K_DIM; ++k) {
            const ulonglong2 bA = *(const ulonglong2*)&sw[k * H_DIM + tx * 4];
            const ulonglong2 bB = *(const ulonglong2*)&sw[k * H_DIM + 64 + tx * 4];

            const unsigned long long x0 = pack2(a0[k]);
            const unsigned long long x1 = pack2(a1[k]);
            const unsigned long long x2 = pack2(a2p[k]);
            const unsigned long long x3 = pack2(a3[k]);

            acc2[0][0] = fma2(x0, bA.x, acc2[0][0]);
            acc2[0][1] = fma2(x0, bA.y, acc2[0][1]);
            acc2[0][2] = fma2(x0, bB.x, acc2[0][2]);
            acc2[0][3] = fma2(x0, bB.y, acc2[0][3]);

            acc2[1][0] = fma2(x1, bA.x, acc2[1][0]);
            acc2[1][1] = fma2(x1, bA.y, acc2[1][1]);
            acc2[1][2] = fma2(x1, bB.x, acc2[1][2]);
            acc2[1][3] = fma2(x1, bB.y, acc2[1][3]);

            acc2[2][0] = fma2(x2, bA.x, acc2[2][0]);
            acc2[2][1] = fma2(x2, bA.y, acc2[2][1]);
            acc2[2][2] = fma2(x2, bB.x, acc2[2][2]);
            acc2[2][3] = fma2(x2, bB.y, acc2[2][3]);

            acc2[3][0] = fma2(x3, bA.x, acc2[3][0]);
            acc2[3][1] = fma2(x3, bA.y, acc2[3][1]);
            acc2[3][2] = fma2(x3, bB.x, acc2[3][2]);
            acc2[3][3] = fma2(x3, bB.y, acc2[3][3]);
        }

        // ---- epilogue: relu + coalesced float4 stores ----
        #pragma unroll
        for (int i = 0; i < 4; ++i) {
            const int b = rowBase + ty * 4 + i;
            if (b < Bn) {
                float lo, hi;
                float4 oA, oB;
                unpack2(acc2[i][0], lo, hi);
                oA.x = fmaxf(lo, 0.f); oA.y = fmaxf(hi, 0.f);
                unpack2(acc2[i][1], lo, hi);
                oA.z = fmaxf(lo, 0.f); oA.w = fmaxf(hi, 0.f);
                unpack2(acc2[i][2], lo, hi);
                oB.x = fmaxf(lo, 0.f); oB.y = fmaxf(hi, 0.f);
                unpack2(acc2[i][3], lo, hi);
                oB.z = fmaxf(lo, 0.f); oB.w = fmaxf(hi, 0.f);

                *(float4*)&out[(size_t)b * H_DIM + tx * 4] = oA;
                *(float4*)&out[(size_t)b * H_DIM + 64 + tx * 4] = oB;
            }
        }
    }
}

extern "C" void kernel_launch(void* const* d_in, const int* in_sizes, int n_in,
                              void* d_out, int out_size)
{
    const int*   nodes  = (const int*)d_in[0];
    const int*   neigh  = (const int*)d_in[1];
    const float* feat   = (const float*)d_in[2];
    const float* weight = (const float*)d_in[3];
    float*       out    = (float*)d_out;
    const int Bn = in_sizes[0];

    cudaFuncSetAttribute(sage_fused_kernel,
                         cudaFuncAttributeMaxDynamicSharedMemorySize, SMEM_BYTES);

    const int grid = (Bn + TILE_M - 1) / TILE_M;
    sage_fused_kernel<<<grid, NTHREADS, SMEM_BYTES>>>(nodes, neigh, feat, weight, out, Bn);
}